// round 1
// baseline (speedup 1.0000x reference)
#include <cuda_runtime.h>
#include <cuda_bf16.h>
#include <cstdint>
#include <cstddef>

// Problem dims
#define BB   128
#define TT   512
#define EE   256
#define UU   512
#define ZZ   2048          // 4*U
#define NCU  64            // u-groups (8 units each)
#define UT   8             // units per CTA group
#define CPC  32            // z-cols per CTA (4 gates * 8 units)

// ---------------- scratch (device globals; no allocations) ----------------
__device__ float g_embT[32000 * EE];                 // tf32-rounded embedding (32.8 MB)
__device__ float g_WxT [EE * ZZ];                    // tf32-rounded Wx (2 MB)
__device__ float g_WhG [NCU * UU * CPC];             // gathered+rounded Wh (4 MB)
__device__ float g_zx  [(size_t)BB * TT * ZZ];       // x@Wx + b, layout [t][b][2048] (512 MB)
__device__ float g_h   [BB * UU];                    // hidden state (tf32-valued fp32)
__device__ float g_c   [BB * UU];                    // cell state fp32

// ---------------- helpers ----------------
__device__ __forceinline__ float round_tf32(float x) {
    uint32_t u;
    asm("cvt.rna.tf32.f32 %0, %1;" : "=r"(u) : "f"(x));
    return __uint_as_float(u);
}
__device__ __forceinline__ uint32_t f2u(float x) { return __float_as_uint(x); }

__device__ __forceinline__ void mma_tf32(float& d0, float& d1, float& d2, float& d3,
                                         uint32_t a0, uint32_t a1, uint32_t a2, uint32_t a3,
                                         uint32_t b0, uint32_t b1) {
    asm volatile(
        "mma.sync.aligned.m16n8k8.row.col.f32.tf32.tf32.f32 "
        "{%0,%1,%2,%3}, {%4,%5,%6,%7}, {%8,%9}, {%0,%1,%2,%3};"
        : "+f"(d0), "+f"(d1), "+f"(d2), "+f"(d3)
        : "r"(a0), "r"(a1), "r"(a2), "r"(a3), "r"(b0), "r"(b1));
}

__device__ __forceinline__ float sigm(float x) { return 1.0f / (1.0f + expf(-x)); }

// ---------------- init kernels (run every launch; deterministic) ----------------
__global__ void k_round(const float* __restrict__ src, float* __restrict__ dst, int n) {
    for (int i = blockIdx.x * blockDim.x + threadIdx.x; i < n; i += gridDim.x * blockDim.x)
        dst[i] = round_tf32(src[i]);
}

// gather Wh columns per u-group: g_WhG[cu][k][jp], jp = gate*8 + j, src col = gate*512 + cu*8 + j
__global__ void k_gather_wh(const float* __restrict__ Wh) {
    int n = NCU * UU * CPC;
    for (int id = blockIdx.x * blockDim.x + threadIdx.x; id < n; id += gridDim.x * blockDim.x) {
        int cu = id >> 14;            // / (512*32)
        int k  = (id >> 5) & 511;
        int jp = id & 31;
        int gate = jp >> 3;
        int j    = jp & 7;
        g_WhG[id] = round_tf32(Wh[(size_t)k * ZZ + gate * UU + cu * UT + j]);
    }
}

__global__ void k_zero_state() {
    int n = BB * UU;
    for (int i = blockIdx.x * blockDim.x + threadIdx.x; i < n; i += gridDim.x * blockDim.x) {
        g_h[i] = 0.0f;
        g_c[i] = 0.0f;
    }
}

// ---------------- phase 1: z_x[t*B+b][n] = emb[sentence[b,t]] @ Wx + bias ----------------
// CTA tile 64x64, K=256 in chunks of 32. 4 warps, each 32x32.
__global__ __launch_bounds__(128) void k_phase1(const int* __restrict__ sentence,
                                                const float* __restrict__ bias) {
    __shared__ float As[64 * 36];
    __shared__ float Bs[32 * 68];
    __shared__ int   toks[64];

    int tid  = threadIdx.x;
    int warp = tid >> 5;
    int lane = tid & 31;
    int tg   = lane & 3;       // thread-in-group
    int gid  = lane >> 2;      // group id

    int m0 = (blockIdx.x >> 5) * 64;   // 1024 m-tiles
    int n0 = (blockIdx.x & 31) * 64;   // 32 n-tiles

    if (tid < 64) {
        int r = m0 + tid;
        int t = r >> 7;        // r / 128
        int b = r & 127;
        toks[tid] = sentence[b * TT + t];
    }
    __syncthreads();

    float acc[2][4][4];
#pragma unroll
    for (int mt = 0; mt < 2; mt++)
#pragma unroll
        for (int nt = 0; nt < 4; nt++)
#pragma unroll
            for (int q = 0; q < 4; q++) acc[mt][nt][q] = 0.0f;

    int wm = (warp >> 1) * 32;
    int wn = (warp & 1) * 32;

    for (int kc = 0; kc < EE; kc += 32) {
        // load A tile 64x32 (embedding-gathered)
        {
            int col = (tid & 7) * 4;
            int row = tid >> 3;  // 0..15
#pragma unroll
            for (int i = 0; i < 4; i++) {
                int r = row + i * 16;
                float4 v = *(const float4*)(g_embT + (size_t)toks[r] * EE + kc + col);
                *(float4*)(As + r * 36 + col) = v;
            }
        }
        // load B tile 32x64 from WxT
        {
            int nc = (tid & 15) * 4;
            int kr = tid >> 4;   // 0..7
#pragma unroll
            for (int i = 0; i < 4; i++) {
                int k = kr + i * 8;
                *(float4*)(Bs + k * 68 + nc) =
                    *(const float4*)(g_WxT + (size_t)(kc + k) * ZZ + n0 + nc);
            }
        }
        __syncthreads();

#pragma unroll
        for (int kk = 0; kk < 4; kk++) {
            uint32_t a[2][4];
#pragma unroll
            for (int mt = 0; mt < 2; mt++) {
                const float* p = As + (wm + mt * 16 + gid) * 36 + kk * 8 + tg;
                a[mt][0] = f2u(p[0]);
                a[mt][1] = f2u(p[8 * 36]);
                a[mt][2] = f2u(p[4]);
                a[mt][3] = f2u(p[8 * 36 + 4]);
            }
            uint32_t bf[4][2];
#pragma unroll
            for (int nt = 0; nt < 4; nt++) {
                int col = wn + nt * 8 + gid;
                int kb  = kk * 8 + tg;
                bf[nt][0] = f2u(Bs[kb * 68 + col]);
                bf[nt][1] = f2u(Bs[(kb + 4) * 68 + col]);
            }
#pragma unroll
            for (int mt = 0; mt < 2; mt++)
#pragma unroll
                for (int nt = 0; nt < 4; nt++)
                    mma_tf32(acc[mt][nt][0], acc[mt][nt][1], acc[mt][nt][2], acc[mt][nt][3],
                             a[mt][0], a[mt][1], a[mt][2], a[mt][3], bf[nt][0], bf[nt][1]);
        }
        __syncthreads();
    }

    // epilogue: add bias, store
#pragma unroll
    for (int mt = 0; mt < 2; mt++) {
#pragma unroll
        for (int nt = 0; nt < 4; nt++) {
            int row = m0 + wm + mt * 16 + gid;
            int col = n0 + wn + nt * 8 + tg * 2;
            float b0 = bias[col], b1 = bias[col + 1];
            size_t base0 = (size_t)row * ZZ + col;
            size_t base2 = (size_t)(row + 8) * ZZ + col;
            g_zx[base0]     = acc[mt][nt][0] + b0;
            g_zx[base0 + 1] = acc[mt][nt][1] + b1;
            g_zx[base2]     = acc[mt][nt][2] + b0;
            g_zx[base2 + 1] = acc[mt][nt][3] + b1;
        }
    }
}

// ---------------- phase 2: one LSTM step ----------------
// Grid 128 CTAs: cu = bx & 63 (u-group, 8 units -> 32 gate cols), mg = bx >> 6 (batch half of 64).
// z[64, 32] = h[64, 512] @ WhG[cu] + z_x, then gate update for owned (b, u).
__global__ __launch_bounds__(128) void k_step(int t) {
    __shared__ float As[64 * 36];   // h chunk
    __shared__ float Bs[32 * 33];   // Wh chunk
    __shared__ float zs[64 * 33];   // z output staging

    int tid  = threadIdx.x;
    int warp = tid >> 5;
    int lane = tid & 31;
    int tg   = lane & 3;
    int gid  = lane >> 2;

    int cu = blockIdx.x & 63;
    int mg = blockIdx.x >> 6;
    int m0 = mg * 64;

    const float* Wp = g_WhG + (size_t)cu * UU * CPC;

    float acc[4][4];
#pragma unroll
    for (int nt = 0; nt < 4; nt++)
#pragma unroll
        for (int q = 0; q < 4; q++) acc[nt][q] = 0.0f;

    for (int kc = 0; kc < UU; kc += 32) {
        // load A: h[m0+row][kc+col], 64x32
        {
            int col = (tid & 7) * 4;
            int row = tid >> 3;
#pragma unroll
            for (int i = 0; i < 4; i++) {
                int r = row + i * 16;
                float4 v = *(const float4*)(g_h + (size_t)(m0 + r) * UU + kc + col);
                *(float4*)(As + r * 36 + col) = v;
            }
        }
        // load B: WhG 32x32
        {
            int c4 = (tid & 7) * 4;
            int kr = tid >> 3;   // 0..15
#pragma unroll
            for (int i = 0; i < 2; i++) {
                int k = kr + i * 16;
                float4 v = *(const float4*)(Wp + (size_t)(kc + k) * CPC + c4);
                float* p = Bs + k * 33 + c4;
                p[0] = v.x; p[1] = v.y; p[2] = v.z; p[3] = v.w;
            }
        }
        __syncthreads();

#pragma unroll
        for (int kk = 0; kk < 4; kk++) {
            const float* p = As + (warp * 16 + gid) * 36 + kk * 8 + tg;
            uint32_t a0 = f2u(p[0]);
            uint32_t a1 = f2u(p[8 * 36]);
            uint32_t a2 = f2u(p[4]);
            uint32_t a3 = f2u(p[8 * 36 + 4]);
#pragma unroll
            for (int nt = 0; nt < 4; nt++) {
                int col = nt * 8 + gid;
                int kb  = kk * 8 + tg;
                uint32_t b0 = f2u(Bs[kb * 33 + col]);
                uint32_t b1 = f2u(Bs[(kb + 4) * 33 + col]);
                mma_tf32(acc[nt][0], acc[nt][1], acc[nt][2], acc[nt][3],
                         a0, a1, a2, a3, b0, b1);
            }
        }
        __syncthreads();
    }

    // stage z to SMEM
#pragma unroll
    for (int nt = 0; nt < 4; nt++) {
        int row = warp * 16 + gid;
        int col = nt * 8 + tg * 2;
        zs[row * 33 + col]           = acc[nt][0];
        zs[row * 33 + col + 1]       = acc[nt][1];
        zs[(row + 8) * 33 + col]     = acc[nt][2];
        zs[(row + 8) * 33 + col + 1] = acc[nt][3];
    }
    __syncthreads();

    // gate update: thread -> (bl = tid/2 in [0,64), half = tid&1 -> 4 units)
    {
        int bl   = tid >> 1;
        int half = tid & 1;
        int j0   = half * 4;
        int b    = m0 + bl;
        size_t zxbase = ((size_t)t * BB + b) * ZZ + cu * UT;
        float4 xi = *(const float4*)(g_zx + zxbase + 0 * UU + j0);
        float4 xf = *(const float4*)(g_zx + zxbase + 1 * UU + j0);
        float4 xg = *(const float4*)(g_zx + zxbase + 2 * UU + j0);
        float4 xo = *(const float4*)(g_zx + zxbase + 3 * UU + j0);
        const float* zrow = zs + bl * 33;
        float xiv[4] = {xi.x, xi.y, xi.z, xi.w};
        float xfv[4] = {xf.x, xf.y, xf.z, xf.w};
        float xgv[4] = {xg.x, xg.y, xg.z, xg.w};
        float xov[4] = {xo.x, xo.y, xo.z, xo.w};
#pragma unroll
        for (int jj = 0; jj < 4; jj++) {
            int jc = j0 + jj;
            float zi = xiv[jj] + zrow[0  + jc];
            float zf = xfv[jj] + zrow[8  + jc];
            float zg = xgv[jj] + zrow[16 + jc];
            float zo = xov[jj] + zrow[24 + jc];
            float ig = sigm(zi);
            float fg = sigm(zf);
            float gg = tanhf(zg);
            float og = sigm(zo);
            int u   = cu * UT + jc;
            int idx = b * UU + u;
            float cn = fg * g_c[idx] + ig * gg;
            g_c[idx] = cn;
            g_h[idx] = round_tf32(og * tanhf(cn));
        }
    }
}

// ---------------- head: per-batch MLP ----------------
__global__ __launch_bounds__(128) void k_head(const float* __restrict__ W1, const float* __restrict__ b1,
                                              const float* __restrict__ W2, const float* __restrict__ b2,
                                              const float* __restrict__ W3, const float* __restrict__ b3,
                                              float* __restrict__ out) {
    __shared__ float hs[UU];
    __shared__ float h1[128];
    __shared__ float red[64];
    int b   = blockIdx.x;
    int tid = threadIdx.x;

    for (int i = tid; i < UU; i += 128) hs[i] = g_h[b * UU + i];
    __syncthreads();

    float a1 = b1[tid];
#pragma unroll 8
    for (int k = 0; k < UU; k++) a1 += hs[k] * W1[k * 128 + tid];
    h1[tid] = fmaxf(a1, 0.0f);
    __syncthreads();

    if (tid < 64) {
        float a2 = b2[tid];
#pragma unroll 8
        for (int k = 0; k < 128; k++) a2 += h1[k] * W2[k * 64 + tid];
        a2 = fmaxf(a2, 0.0f);
        red[tid] = a2 * W3[tid];
    }
    __syncthreads();

    if (tid == 0) {
        float s = b3[0];
#pragma unroll 8
        for (int k = 0; k < 64; k++) s += red[k];
        out[b] = 1.0f / (1.0f + expf(-s));
    }
}

// ---------------- launch ----------------
extern "C" void kernel_launch(void* const* d_in, const int* in_sizes, int n_in,
                              void* d_out, int out_size) {
    const int*   sentence = (const int*)  d_in[0];
    const float* emb      = (const float*)d_in[1];
    const float* Wx       = (const float*)d_in[2];
    const float* Wh       = (const float*)d_in[3];
    const float* bvec     = (const float*)d_in[4];
    const float* W1       = (const float*)d_in[5];
    const float* b1       = (const float*)d_in[6];
    const float* W2       = (const float*)d_in[7];
    const float* b2       = (const float*)d_in[8];
    const float* W3       = (const float*)d_in[9];
    const float* b3       = (const float*)d_in[10];
    float* out = (float*)d_out;

    float* p_embT; cudaGetSymbolAddress((void**)&p_embT, g_embT);
    float* p_WxT;  cudaGetSymbolAddress((void**)&p_WxT,  g_WxT);

    k_round<<<2048, 256>>>(emb, p_embT, 32000 * EE);
    k_round<<<512, 256>>>(Wx, p_WxT, EE * ZZ);
    k_gather_wh<<<1024, 256>>>(Wh);
    k_zero_state<<<128, 256>>>();

    k_phase1<<<32768, 128>>>(sentence, bvec);

    for (int t = 0; t < TT; t++) {
        k_step<<<128, 128>>>(t);
    }

    k_head<<<128, 128>>>(W1, b1, W2, b2, W3, b3, out);
}

// round 2
// speedup vs baseline: 1.9146x; 1.9146x over previous
#include <cuda_runtime.h>
#include <cuda_bf16.h>
#include <cstdint>
#include <cstddef>

// Problem dims
#define BB   128
#define TT   512
#define EE   256
#define UU   512
#define ZZ   2048          // 4*U
#define NCU  64            // u-groups (8 units each)
#define UT   8             // units per CTA group
#define CPC  32            // z-cols per CTA (4 gates * 8 units)

typedef __nv_bfloat16 bf16;

// ---------------- scratch (device globals; no allocations) ----------------
__device__ __align__(16) bf16  g_emb16[32000 * EE];          // bf16 embedding (16.4 MB)
__device__ __align__(16) bf16  g_WxGt [ZZ * EE];             // gathered Wx, [gc][k] (1 MB)
__device__ __align__(16) bf16  g_WhGt [NCU * CPC * UU];      // gathered Wh, [cu][jp][k] (2 MB)
__device__ __align__(16) float g_bG   [ZZ];                  // gathered bias
__device__ __align__(16) float g_zx   [(size_t)BB * TT * ZZ];// x@Wx + b, [t][b][gathered 2048] (512 MB)
__device__ __align__(16) bf16  g_h16  [BB * UU];             // hidden state bf16
__device__ __align__(16) float g_c    [BB * UU];             // cell state fp32

// gather map: gc -> original column
__device__ __forceinline__ int orig_col(int gc) {
    int cu   = gc >> 5;
    int gate = (gc >> 3) & 3;
    int j    = gc & 7;
    return gate * UU + cu * UT + j;
}

__device__ __forceinline__ float sigm(float x) { return 1.0f / (1.0f + expf(-x)); }

__device__ __forceinline__ void mma_bf16(float& d0, float& d1, float& d2, float& d3,
                                         uint32_t a0, uint32_t a1, uint32_t a2, uint32_t a3,
                                         uint32_t b0, uint32_t b1) {
    asm volatile(
        "mma.sync.aligned.m16n8k16.row.col.f32.bf16.bf16.f32 "
        "{%0,%1,%2,%3}, {%4,%5,%6,%7}, {%8,%9}, {%0,%1,%2,%3};"
        : "+f"(d0), "+f"(d1), "+f"(d2), "+f"(d3)
        : "r"(a0), "r"(a1), "r"(a2), "r"(a3), "r"(b0), "r"(b1));
}

__device__ __forceinline__ uint32_t ldpair(const bf16* p) {
    return *(const uint32_t*)p;
}

// ---------------- init kernels ----------------
__global__ void k_cvt_emb(const float* __restrict__ src) {
    int n4 = 32000 * EE / 4;
    for (int i = blockIdx.x * blockDim.x + threadIdx.x; i < n4; i += gridDim.x * blockDim.x) {
        float4 v = *(const float4*)(src + (size_t)i * 4);
        bf16* d = g_emb16 + (size_t)i * 4;
        d[0] = __float2bfloat16(v.x);
        d[1] = __float2bfloat16(v.y);
        d[2] = __float2bfloat16(v.z);
        d[3] = __float2bfloat16(v.w);
    }
}

__global__ void k_gather_wx(const float* __restrict__ Wx, const float* __restrict__ bvec) {
    int n = ZZ * EE;
    for (int i = blockIdx.x * blockDim.x + threadIdx.x; i < n; i += gridDim.x * blockDim.x) {
        int gc = i >> 8;          // / 256
        int k  = i & 255;
        g_WxGt[i] = __float2bfloat16(Wx[(size_t)k * ZZ + orig_col(gc)]);
    }
    int t = blockIdx.x * blockDim.x + threadIdx.x;
    if (t < ZZ) g_bG[t] = bvec[orig_col(t)];
}

__global__ void k_gather_wh(const float* __restrict__ Wh) {
    int n = NCU * CPC * UU;
    for (int i = blockIdx.x * blockDim.x + threadIdx.x; i < n; i += gridDim.x * blockDim.x) {
        int cu = i >> 14;             // / (32*512)
        int jp = (i >> 9) & 31;
        int k  = i & 511;
        int gate = jp >> 3;
        int j    = jp & 7;
        g_WhGt[i] = __float2bfloat16(Wh[(size_t)k * ZZ + gate * UU + cu * UT + j]);
    }
}

__global__ void k_zero_state() {
    int n = BB * UU;
    for (int i = blockIdx.x * blockDim.x + threadIdx.x; i < n; i += gridDim.x * blockDim.x) {
        g_c[i]   = 0.0f;
        g_h16[i] = __float2bfloat16(0.0f);
    }
}

// ---------------- phase 1: z_x = emb[sentence] @ Wx + b (gathered cols) ----------------
// grid: (t, ntile): blockIdx.x>>5 = t in [0,512), (blockIdx.x&31)*64 = n0.
// CTA tile: 128 (all b at this t) x 64 gathered cols. 256 threads, 8 warps (32x32 each).
__global__ __launch_bounds__(256) void k_phase1(const int* __restrict__ sentence) {
    __shared__ __align__(16) bf16 As[128 * 72];
    __shared__ __align__(16) bf16 Bs[64 * 72];
    __shared__ int toks[128];

    int tid  = threadIdx.x;
    int warp = tid >> 5;
    int lane = tid & 31;
    int tg   = lane & 3;
    int gid  = lane >> 2;

    int t  = blockIdx.x >> 5;
    int n0 = (blockIdx.x & 31) * 64;

    if (tid < 128) toks[tid] = sentence[tid * TT + t];
    __syncthreads();

    float acc[2][4][4];
#pragma unroll
    for (int mt = 0; mt < 2; mt++)
#pragma unroll
        for (int nt = 0; nt < 4; nt++)
#pragma unroll
            for (int q = 0; q < 4; q++) acc[mt][nt][q] = 0.0f;

    int wm = (warp >> 1) * 32;
    int wn = (warp & 1) * 32;

    for (int kc = 0; kc < EE; kc += 64) {
        // A: 128x64 bf16, 1024 uint4, 4 per thread
#pragma unroll
        for (int r = 0; r < 4; r++) {
            int i   = tid + 256 * r;
            int row = i >> 3;
            int seg = i & 7;
            *(uint4*)(As + row * 72 + seg * 8) =
                *(const uint4*)(g_emb16 + (size_t)toks[row] * EE + kc + seg * 8);
        }
        // B: 64x64 bf16 (rows = gathered n, cols = k), 512 uint4, 2 per thread
#pragma unroll
        for (int r = 0; r < 2; r++) {
            int i   = tid + 256 * r;
            int n   = i >> 3;
            int seg = i & 7;
            *(uint4*)(Bs + n * 72 + seg * 8) =
                *(const uint4*)(g_WxGt + (size_t)(n0 + n) * EE + kc + seg * 8);
        }
        __syncthreads();

#pragma unroll
        for (int k16 = 0; k16 < 4; k16++) {
            int kb = k16 * 16;
            uint32_t a[2][4];
#pragma unroll
            for (int mt = 0; mt < 2; mt++) {
                const bf16* p = As + (wm + mt * 16 + gid) * 72 + kb + tg * 2;
                a[mt][0] = ldpair(p);
                a[mt][1] = ldpair(p + 8 * 72);
                a[mt][2] = ldpair(p + 8);
                a[mt][3] = ldpair(p + 8 * 72 + 8);
            }
            uint32_t bfr[4][2];
#pragma unroll
            for (int nt = 0; nt < 4; nt++) {
                const bf16* p = Bs + (wn + nt * 8 + gid) * 72 + kb + tg * 2;
                bfr[nt][0] = ldpair(p);
                bfr[nt][1] = ldpair(p + 8);
            }
#pragma unroll
            for (int mt = 0; mt < 2; mt++)
#pragma unroll
                for (int nt = 0; nt < 4; nt++)
                    mma_bf16(acc[mt][nt][0], acc[mt][nt][1], acc[mt][nt][2], acc[mt][nt][3],
                             a[mt][0], a[mt][1], a[mt][2], a[mt][3],
                             bfr[nt][0], bfr[nt][1]);
        }
        __syncthreads();
    }

    // epilogue: add gathered bias, store fp32
#pragma unroll
    for (int mt = 0; mt < 2; mt++) {
#pragma unroll
        for (int nt = 0; nt < 4; nt++) {
            int b   = wm + mt * 16 + gid;         // batch row
            int col = n0 + wn + nt * 8 + tg * 2;  // gathered col
            float bi0 = g_bG[col], bi1 = g_bG[col + 1];
            size_t r0 = ((size_t)t * BB + b) * ZZ + col;
            size_t r2 = ((size_t)t * BB + b + 8) * ZZ + col;
            float2 v0 = { acc[mt][nt][0] + bi0, acc[mt][nt][1] + bi1 };
            float2 v2 = { acc[mt][nt][2] + bi0, acc[mt][nt][3] + bi1 };
            *(float2*)(g_zx + r0) = v0;
            *(float2*)(g_zx + r2) = v2;
        }
    }
}

// ---------------- phase 2: one LSTM step ----------------
// 128 CTAs: cu = bx&63, mg = bx>>6, m0 = mg*64. Output z[64 b][32 gathered cols].
// 256 threads, 8 warps; warp tile 16x16 (wm=(warp>>1)*16, wn=(warp&1)*16).
__global__ __launch_bounds__(256) void k_step(int t) {
    __shared__ __align__(16) bf16  As[64 * 72];      // h chunk; reused as zs (fp32 64x33) after loop
    __shared__ __align__(16) bf16  Bs[32 * 72];      // Wh chunk
    __shared__ __align__(16) float zxs[64 * 36];     // z_x block

    int tid  = threadIdx.x;
    int warp = tid >> 5;
    int lane = tid & 31;
    int tg   = lane & 3;
    int gid  = lane >> 2;

    int cu = blockIdx.x & 63;
    int mg = blockIdx.x >> 6;
    int m0 = mg * 64;

    // Early: stage z_x block (64 rows x 32 f32, contiguous 128B per row) into smem
#pragma unroll
    for (int r = 0; r < 2; r++) {
        int i   = tid + 256 * r;
        int row = i >> 3;
        int seg = i & 7;
        *(uint4*)(zxs + row * 36 + seg * 4) =
            *(const uint4*)(g_zx + ((size_t)t * BB + m0 + row) * ZZ + cu * CPC + seg * 4);
    }

    const bf16* Wp = g_WhGt + (size_t)cu * CPC * UU;

    float acc[2][4];
#pragma unroll
    for (int nt = 0; nt < 2; nt++)
#pragma unroll
        for (int q = 0; q < 4; q++) acc[nt][q] = 0.0f;

    int wm = (warp >> 1) * 16;
    int wn = (warp & 1) * 16;

    for (int kc = 0; kc < UU; kc += 64) {
        // A: h 64x64 bf16, 512 uint4, 2/thread
#pragma unroll
        for (int r = 0; r < 2; r++) {
            int i   = tid + 256 * r;
            int row = i >> 3;
            int seg = i & 7;
            *(uint4*)(As + row * 72 + seg * 8) =
                *(const uint4*)(g_h16 + (size_t)(m0 + row) * UU + kc + seg * 8);
        }
        // B: Wh 32x64 bf16 ([jp][k] layout), 256 uint4, 1/thread
        {
            int n   = tid >> 3;
            int seg = tid & 7;
            *(uint4*)(Bs + n * 72 + seg * 8) =
                *(const uint4*)(Wp + (size_t)n * UU + kc + seg * 8);
        }
        __syncthreads();

#pragma unroll
        for (int k16 = 0; k16 < 4; k16++) {
            int kb = k16 * 16;
            const bf16* pa = As + (wm + gid) * 72 + kb + tg * 2;
            uint32_t a0 = ldpair(pa);
            uint32_t a1 = ldpair(pa + 8 * 72);
            uint32_t a2 = ldpair(pa + 8);
            uint32_t a3 = ldpair(pa + 8 * 72 + 8);
#pragma unroll
            for (int nt = 0; nt < 2; nt++) {
                const bf16* pb = Bs + (wn + nt * 8 + gid) * 72 + kb + tg * 2;
                uint32_t b0 = ldpair(pb);
                uint32_t b1 = ldpair(pb + 8);
                mma_bf16(acc[nt][0], acc[nt][1], acc[nt][2], acc[nt][3],
                         a0, a1, a2, a3, b0, b1);
            }
        }
        __syncthreads();
    }

    // stage z (fp32) into As region
    float* zs = (float*)As;   // 64 x 33 floats = 8448 B <= 9216 B
#pragma unroll
    for (int nt = 0; nt < 2; nt++) {
        int row = wm + gid;
        int col = wn + nt * 8 + tg * 2;
        zs[row * 33 + col]           = acc[nt][0];
        zs[row * 33 + col + 1]       = acc[nt][1];
        zs[(row + 8) * 33 + col]     = acc[nt][2];
        zs[(row + 8) * 33 + col + 1] = acc[nt][3];
    }
    __syncthreads();

    // gate update: thread -> (b = tid>>2, jh = tid&3), handles units j = jh*2, jh*2+1
    {
        int b  = tid >> 2;
        int jh = tid & 3;
        const float* zxr = zxs + b * 36;
        const float* zr  = zs  + b * 33;
        size_t idx = (size_t)(m0 + b) * UU + cu * UT + jh * 2;
        float2 c2 = *(float2*)(g_c + idx);
        float cv[2] = { c2.x, c2.y };
        float hv[2];
#pragma unroll
        for (int s = 0; s < 2; s++) {
            int jc = jh * 2 + s;
            float zi = zxr[jc]      + zr[jc];
            float zf = zxr[8 + jc]  + zr[8 + jc];
            float zg = zxr[16 + jc] + zr[16 + jc];
            float zo = zxr[24 + jc] + zr[24 + jc];
            float ig = sigm(zi);
            float fg = sigm(zf);
            float gg = tanhf(zg);
            float og = sigm(zo);
            float cn = fg * cv[s] + ig * gg;
            cv[s] = cn;
            hv[s] = og * tanhf(cn);
        }
        *(float2*)(g_c + idx) = make_float2(cv[0], cv[1]);
        __nv_bfloat162 h2;
        h2.x = __float2bfloat16(hv[0]);
        h2.y = __float2bfloat16(hv[1]);
        *(__nv_bfloat162*)(g_h16 + idx) = h2;
    }
}

// ---------------- head: per-batch MLP ----------------
__global__ __launch_bounds__(128) void k_head(const float* __restrict__ W1, const float* __restrict__ b1,
                                              const float* __restrict__ W2, const float* __restrict__ b2,
                                              const float* __restrict__ W3, const float* __restrict__ b3,
                                              float* __restrict__ out) {
    __shared__ float hs[UU];
    __shared__ float h1[128];
    __shared__ float red[64];
    int b   = blockIdx.x;
    int tid = threadIdx.x;

    for (int i = tid; i < UU; i += 128) hs[i] = __bfloat162float(g_h16[b * UU + i]);
    __syncthreads();

    float a1 = b1[tid];
#pragma unroll 8
    for (int k = 0; k < UU; k++) a1 += hs[k] * W1[k * 128 + tid];
    h1[tid] = fmaxf(a1, 0.0f);
    __syncthreads();

    if (tid < 64) {
        float a2 = b2[tid];
#pragma unroll 8
        for (int k = 0; k < 128; k++) a2 += h1[k] * W2[k * 64 + tid];
        a2 = fmaxf(a2, 0.0f);
        red[tid] = a2 * W3[tid];
    }
    __syncthreads();

    if (tid == 0) {
        float s = b3[0];
#pragma unroll 8
        for (int k = 0; k < 64; k++) s += red[k];
        out[b] = 1.0f / (1.0f + expf(-s));
    }
}

// ---------------- launch ----------------
extern "C" void kernel_launch(void* const* d_in, const int* in_sizes, int n_in,
                              void* d_out, int out_size) {
    const int*   sentence = (const int*)  d_in[0];
    const float* emb      = (const float*)d_in[1];
    const float* Wx       = (const float*)d_in[2];
    const float* Wh       = (const float*)d_in[3];
    const float* bvec     = (const float*)d_in[4];
    const float* W1       = (const float*)d_in[5];
    const float* b1       = (const float*)d_in[6];
    const float* W2       = (const float*)d_in[7];
    const float* b2       = (const float*)d_in[8];
    const float* W3       = (const float*)d_in[9];
    const float* b3       = (const float*)d_in[10];
    float* out = (float*)d_out;

    k_cvt_emb<<<4096, 256>>>(emb);
    k_gather_wx<<<2048, 256>>>(Wx, bvec);
    k_gather_wh<<<4096, 256>>>(Wh);
    k_zero_state<<<256, 256>>>();

    k_phase1<<<16384, 256>>>(sentence);

    for (int t = 0; t < TT; t++) {
        k_step<<<128, 256>>>(t);
    }

    k_head<<<128, 128>>>(W1, b1, W2, b2, W3, b3, out);
}

// round 3
// speedup vs baseline: 2.5549x; 1.3344x over previous
#include <cuda_runtime.h>
#include <cuda_bf16.h>
#include <cstdint>
#include <cstddef>

// Problem dims
#define BB   128
#define TT   512
#define EE   256
#define UU   512
#define ZZ   2048          // 4*U
#define NCU  64            // u-groups (8 units each)
#define UT   8             // units per CTA group
#define CPC  32            // z-cols per CTA (4 gates * 8 units)
#define NCTA 128           // persistent grid

typedef __nv_bfloat16 bf16;

// ---------------- scratch (device globals; no allocations) ----------------
__device__ __align__(16) bf16  g_emb16[32000 * EE];          // bf16 embedding (16.4 MB)
__device__ __align__(16) bf16  g_WxGt [ZZ * EE];             // gathered Wx, [gc][k] (1 MB)
__device__ __align__(16) bf16  g_WhGt [NCU * CPC * UU];      // gathered Wh, [cu][jp][k] (2 MB)
__device__ __align__(16) float g_bG   [ZZ];                  // gathered bias
__device__ __align__(16) float g_zx   [(size_t)BB * TT * ZZ];// x@Wx + b, [t][b][gathered 2048] (512 MB)
__device__ __align__(16) bf16  g_hbuf [2 * BB * UU];         // double-buffered hidden state (bf16)
__device__ unsigned g_count;                                 // barrier arrival counter
__device__ unsigned g_release;                               // barrier release epoch

// gather map: gc -> original column
__device__ __forceinline__ int orig_col(int gc) {
    int cu   = gc >> 5;
    int gate = (gc >> 3) & 3;
    int j    = gc & 7;
    return gate * UU + cu * UT + j;
}

__device__ __forceinline__ float sigm(float x) { return 1.0f / (1.0f + expf(-x)); }

__device__ __forceinline__ void mma_bf16(float& d0, float& d1, float& d2, float& d3,
                                         uint32_t a0, uint32_t a1, uint32_t a2, uint32_t a3,
                                         uint32_t b0, uint32_t b1) {
    asm volatile(
        "mma.sync.aligned.m16n8k16.row.col.f32.bf16.bf16.f32 "
        "{%0,%1,%2,%3}, {%4,%5,%6,%7}, {%8,%9}, {%0,%1,%2,%3};"
        : "+f"(d0), "+f"(d1), "+f"(d2), "+f"(d3)
        : "r"(a0), "r"(a1), "r"(a2), "r"(a3), "r"(b0), "r"(b1));
}

__device__ __forceinline__ uint32_t ldpair(const bf16* p) {
    return *(const uint32_t*)p;
}

// ---------------- init kernels ----------------
__global__ void k_cvt_emb(const float* __restrict__ src) {
    int n4 = 32000 * EE / 4;
    for (int i = blockIdx.x * blockDim.x + threadIdx.x; i < n4; i += gridDim.x * blockDim.x) {
        float4 v = *(const float4*)(src + (size_t)i * 4);
        bf16* d = g_emb16 + (size_t)i * 4;
        d[0] = __float2bfloat16(v.x);
        d[1] = __float2bfloat16(v.y);
        d[2] = __float2bfloat16(v.z);
        d[3] = __float2bfloat16(v.w);
    }
}

__global__ void k_gather_wx(const float* __restrict__ Wx, const float* __restrict__ bvec) {
    int n = ZZ * EE;
    for (int i = blockIdx.x * blockDim.x + threadIdx.x; i < n; i += gridDim.x * blockDim.x) {
        int gc = i >> 8;          // / 256
        int k  = i & 255;
        g_WxGt[i] = __float2bfloat16(Wx[(size_t)k * ZZ + orig_col(gc)]);
    }
    int t = blockIdx.x * blockDim.x + threadIdx.x;
    if (t < ZZ) g_bG[t] = bvec[orig_col(t)];
}

__global__ void k_gather_wh(const float* __restrict__ Wh) {
    int n = NCU * CPC * UU;
    for (int i = blockIdx.x * blockDim.x + threadIdx.x; i < n; i += gridDim.x * blockDim.x) {
        int cu = i >> 14;             // / (32*512)
        int jp = (i >> 9) & 31;
        int k  = i & 511;
        int gate = jp >> 3;
        int j    = jp & 7;
        g_WhGt[i] = __float2bfloat16(Wh[(size_t)k * ZZ + gate * UU + cu * UT + j]);
    }
}

__global__ void k_zero_state() {
    int tid = blockIdx.x * blockDim.x + threadIdx.x;
    // zero h buffer 0 (the one step 0 reads)
    int n = BB * UU;
    for (int i = tid; i < n; i += gridDim.x * blockDim.x)
        g_hbuf[i] = __float2bfloat16(0.0f);
    if (tid == 0) { g_count = 0; g_release = 0; }
}

// ---------------- phase 1: z_x = emb[sentence] @ Wx + b (gathered cols) ----------------
__global__ __launch_bounds__(256) void k_phase1(const int* __restrict__ sentence) {
    __shared__ __align__(16) bf16 As[128 * 72];
    __shared__ __align__(16) bf16 Bs[64 * 72];
    __shared__ int toks[128];

    int tid  = threadIdx.x;
    int warp = tid >> 5;
    int lane = tid & 31;
    int tg   = lane & 3;
    int gid  = lane >> 2;

    int t  = blockIdx.x >> 5;
    int n0 = (blockIdx.x & 31) * 64;

    if (tid < 128) toks[tid] = sentence[tid * TT + t];
    __syncthreads();

    float acc[2][4][4];
#pragma unroll
    for (int mt = 0; mt < 2; mt++)
#pragma unroll
        for (int nt = 0; nt < 4; nt++)
#pragma unroll
            for (int q = 0; q < 4; q++) acc[mt][nt][q] = 0.0f;

    int wm = (warp >> 1) * 32;
    int wn = (warp & 1) * 32;

    for (int kc = 0; kc < EE; kc += 64) {
#pragma unroll
        for (int r = 0; r < 4; r++) {
            int i   = tid + 256 * r;
            int row = i >> 3;
            int seg = i & 7;
            *(uint4*)(As + row * 72 + seg * 8) =
                *(const uint4*)(g_emb16 + (size_t)toks[row] * EE + kc + seg * 8);
        }
#pragma unroll
        for (int r = 0; r < 2; r++) {
            int i   = tid + 256 * r;
            int n   = i >> 3;
            int seg = i & 7;
            *(uint4*)(Bs + n * 72 + seg * 8) =
                *(const uint4*)(g_WxGt + (size_t)(n0 + n) * EE + kc + seg * 8);
        }
        __syncthreads();

#pragma unroll
        for (int k16 = 0; k16 < 4; k16++) {
            int kb = k16 * 16;
            uint32_t a[2][4];
#pragma unroll
            for (int mt = 0; mt < 2; mt++) {
                const bf16* p = As + (wm + mt * 16 + gid) * 72 + kb + tg * 2;
                a[mt][0] = ldpair(p);
                a[mt][1] = ldpair(p + 8 * 72);
                a[mt][2] = ldpair(p + 8);
                a[mt][3] = ldpair(p + 8 * 72 + 8);
            }
            uint32_t bfr[4][2];
#pragma unroll
            for (int nt = 0; nt < 4; nt++) {
                const bf16* p = Bs + (wn + nt * 8 + gid) * 72 + kb + tg * 2;
                bfr[nt][0] = ldpair(p);
                bfr[nt][1] = ldpair(p + 8);
            }
#pragma unroll
            for (int mt = 0; mt < 2; mt++)
#pragma unroll
                for (int nt = 0; nt < 4; nt++)
                    mma_bf16(acc[mt][nt][0], acc[mt][nt][1], acc[mt][nt][2], acc[mt][nt][3],
                             a[mt][0], a[mt][1], a[mt][2], a[mt][3],
                             bfr[nt][0], bfr[nt][1]);
        }
        __syncthreads();
    }

#pragma unroll
    for (int mt = 0; mt < 2; mt++) {
#pragma unroll
        for (int nt = 0; nt < 4; nt++) {
            int b   = wm + mt * 16 + gid;
            int col = n0 + wn + nt * 8 + tg * 2;
            float bi0 = g_bG[col], bi1 = g_bG[col + 1];
            size_t r0 = ((size_t)t * BB + b) * ZZ + col;
            size_t r2 = ((size_t)t * BB + b + 8) * ZZ + col;
            float2 v0 = { acc[mt][nt][0] + bi0, acc[mt][nt][1] + bi1 };
            float2 v2 = { acc[mt][nt][2] + bi0, acc[mt][nt][3] + bi1 };
            *(float2*)(g_zx + r0) = v0;
            *(float2*)(g_zx + r2) = v2;
        }
    }
}

// ---------------- phase 2: persistent recurrence over all 512 steps ----------------
// 128 CTAs (co-resident): cu = bx&63, mg = bx>>6. Per step: z = h@WhG[cu] + z_x, gate math.
// Wh slice held in smem for the whole kernel; c held in registers; h ping-pongs in global.
__global__ __launch_bounds__(256) void k_recur() {
    __shared__ __align__(16) bf16 Bs[32 * 520];     // Wh slice, resident all steps (33.3 KB)
    __shared__ __align__(16) bf16 As[64 * 72];      // h chunk; reused as fp32 zs after GEMM

    int tid  = threadIdx.x;
    int warp = tid >> 5;
    int lane = tid & 31;
    int tg   = lane & 3;
    int gid  = lane >> 2;

    int cu = blockIdx.x & 63;
    int mg = blockIdx.x >> 6;
    int m0 = mg * 64;

    int wm = (warp >> 1) * 16;
    int wn = (warp & 1) * 16;

    // preload Wh slice (32 x 512 bf16), padded stride 520
    {
        const bf16* Wp = g_WhGt + (size_t)cu * CPC * UU;
        for (int i = tid; i < 2048; i += 256) {
            int n   = i >> 6;
            int seg = i & 63;
            *(uint4*)(Bs + n * 520 + seg * 8) = *(const uint4*)(Wp + n * UU + seg * 8);
        }
    }

    // gate-update ownership: b row, unit pair
    int bl = tid >> 2;
    int jh = tid & 3;
    float c0 = 0.0f, c1 = 0.0f;          // cell state lives in registers

    for (int t = 0; t < TT; t++) {
        int p = t & 1;
        const bf16* hsrc = g_hbuf + p * (BB * UU);
        bf16*       hdst = g_hbuf + (p ^ 1) * (BB * UU);

        // prefetch z_x row segment (coalesced: 4 threads cover each 128B row)
        const float* zxp = g_zx + ((size_t)t * BB + m0 + bl) * ZZ + cu * CPC;
        float2 zx0 = *(const float2*)(zxp + 0  + jh * 2);
        float2 zx1 = *(const float2*)(zxp + 8  + jh * 2);
        float2 zx2 = *(const float2*)(zxp + 16 + jh * 2);
        float2 zx3 = *(const float2*)(zxp + 24 + jh * 2);

        float acc[2][4];
#pragma unroll
        for (int nt = 0; nt < 2; nt++)
#pragma unroll
            for (int q = 0; q < 4; q++) acc[nt][q] = 0.0f;

        for (int kc = 0; kc < UU; kc += 64) {
            // stage h 64x64 chunk
#pragma unroll
            for (int r = 0; r < 2; r++) {
                int i   = tid + 256 * r;
                int row = i >> 3;
                int seg = i & 7;
                *(uint4*)(As + row * 72 + seg * 8) =
                    *(const uint4*)(hsrc + (size_t)(m0 + row) * UU + kc + seg * 8);
            }
            __syncthreads();

#pragma unroll
            for (int k16 = 0; k16 < 4; k16++) {
                int kb = k16 * 16;
                const bf16* pa = As + (wm + gid) * 72 + kb + tg * 2;
                uint32_t a0 = ldpair(pa);
                uint32_t a1 = ldpair(pa + 8 * 72);
                uint32_t a2 = ldpair(pa + 8);
                uint32_t a3 = ldpair(pa + 8 * 72 + 8);
#pragma unroll
                for (int nt = 0; nt < 2; nt++) {
                    const bf16* pb = Bs + (size_t)(wn + nt * 8 + gid) * 520 + kc + kb + tg * 2;
                    uint32_t b0 = ldpair(pb);
                    uint32_t b1 = ldpair(pb + 8);
                    mma_bf16(acc[nt][0], acc[nt][1], acc[nt][2], acc[nt][3],
                             a0, a1, a2, a3, b0, b1);
                }
            }
            __syncthreads();
        }

        // stage z (fp32) into As region
        float* zs = (float*)As;   // 64 x 33 floats = 8448 B
#pragma unroll
        for (int nt = 0; nt < 2; nt++) {
            int row = wm + gid;
            int col = wn + nt * 8 + tg * 2;
            zs[row * 33 + col]           = acc[nt][0];
            zs[row * 33 + col + 1]       = acc[nt][1];
            zs[(row + 8) * 33 + col]     = acc[nt][2];
            zs[(row + 8) * 33 + col + 1] = acc[nt][3];
        }
        __syncthreads();

        // gate update (c in registers)
        {
            const float* zr = zs + bl * 33;
            float hv0, hv1;
            {
                int jc = jh * 2;
                float zi = zx0.x + zr[jc];
                float zf = zx1.x + zr[8 + jc];
                float zg = zx2.x + zr[16 + jc];
                float zo = zx3.x + zr[24 + jc];
                float ig = sigm(zi), fg = sigm(zf), gg = tanhf(zg), og = sigm(zo);
                c0 = fg * c0 + ig * gg;
                hv0 = og * tanhf(c0);
            }
            {
                int jc = jh * 2 + 1;
                float zi = zx0.y + zr[jc];
                float zf = zx1.y + zr[8 + jc];
                float zg = zx2.y + zr[16 + jc];
                float zo = zx3.y + zr[24 + jc];
                float ig = sigm(zi), fg = sigm(zf), gg = tanhf(zg), og = sigm(zo);
                c1 = fg * c1 + ig * gg;
                hv1 = og * tanhf(c1);
            }
            __nv_bfloat162 h2;
            h2.x = __float2bfloat16(hv0);
            h2.y = __float2bfloat16(hv1);
            *(__nv_bfloat162*)(hdst + (size_t)(m0 + bl) * UU + cu * UT + jh * 2) = h2;
        }
        __syncthreads();   // all h writes issued before barrier arrival

        // grid-wide barrier (sense via monotonically increasing epoch)
        if (tid == 0) {
            __threadfence();
            unsigned arr = atomicAdd(&g_count, 1u);
            if (arr == NCTA - 1) {
                g_count = 0;
                __threadfence();
                *(volatile unsigned*)&g_release = (unsigned)(t + 1);
            } else {
                while (*(volatile unsigned*)&g_release < (unsigned)(t + 1)) { }
                __threadfence();
            }
        }
        __syncthreads();
    }
}

// ---------------- head: per-batch MLP (reads hbuf[0], where h ends after 512 steps) ----------------
__global__ __launch_bounds__(128) void k_head(const float* __restrict__ W1, const float* __restrict__ b1,
                                              const float* __restrict__ W2, const float* __restrict__ b2,
                                              const float* __restrict__ W3, const float* __restrict__ b3,
                                              float* __restrict__ out) {
    __shared__ float hs[UU];
    __shared__ float h1[128];
    __shared__ float red[64];
    int b   = blockIdx.x;
    int tid = threadIdx.x;

    for (int i = tid; i < UU; i += 128) hs[i] = __bfloat162float(g_hbuf[b * UU + i]);
    __syncthreads();

    float a1 = b1[tid];
#pragma unroll 8
    for (int k = 0; k < UU; k++) a1 += hs[k] * W1[k * 128 + tid];
    h1[tid] = fmaxf(a1, 0.0f);
    __syncthreads();

    if (tid < 64) {
        float a2 = b2[tid];
#pragma unroll 8
        for (int k = 0; k < 128; k++) a2 += h1[k] * W2[k * 64 + tid];
        a2 = fmaxf(a2, 0.0f);
        red[tid] = a2 * W3[tid];
    }
    __syncthreads();

    if (tid == 0) {
        float s = b3[0];
#pragma unroll 8
        for (int k = 0; k < 64; k++) s += red[k];
        out[b] = 1.0f / (1.0f + expf(-s));
    }
}

// ---------------- launch ----------------
extern "C" void kernel_launch(void* const* d_in, const int* in_sizes, int n_in,
                              void* d_out, int out_size) {
    const int*   sentence = (const int*)  d_in[0];
    const float* emb      = (const float*)d_in[1];
    const float* Wx       = (const float*)d_in[2];
    const float* Wh       = (const float*)d_in[3];
    const float* bvec     = (const float*)d_in[4];
    const float* W1       = (const float*)d_in[5];
    const float* b1       = (const float*)d_in[6];
    const float* W2       = (const float*)d_in[7];
    const float* b2       = (const float*)d_in[8];
    const float* W3       = (const float*)d_in[9];
    const float* b3       = (const float*)d_in[10];
    float* out = (float*)d_out;

    k_cvt_emb<<<4096, 256>>>(emb);
    k_gather_wx<<<2048, 256>>>(Wx, bvec);
    k_gather_wh<<<4096, 256>>>(Wh);
    k_zero_state<<<256, 256>>>();

    k_phase1<<<16384, 256>>>(sentence);

    k_recur<<<NCTA, 256>>>();

    k_head<<<128, 128>>>(W1, b1, W2, b2, W3, b3, out);
}

// round 4
// speedup vs baseline: 4.0688x; 1.5926x over previous
#include <cuda_runtime.h>
#include <cuda_bf16.h>
#include <cstdint>
#include <cstddef>

// Problem dims
#define BB   128
#define TT   512
#define EE   256
#define UU   512
#define ZZ   2048          // 4*U
#define NCU  64            // u-groups (8 units each)
#define UT   8             // units per CTA group
#define CPC  32            // z-cols per CTA (4 gates * 8 units)
#define NCTA 128           // persistent grid

typedef __nv_bfloat16 bf16;

// ---------------- scratch (device globals; no allocations) ----------------
__device__ __align__(16) bf16  g_emb16[32000 * EE];          // bf16 embedding (16.4 MB)
__device__ __align__(16) bf16  g_WxGt [ZZ * EE];             // gathered Wx, [gc][k] (1 MB)
__device__ __align__(16) bf16  g_WhGt [NCU * CPC * UU];      // gathered Wh, [cu][jp][k] (2 MB)
__device__ __align__(16) float g_bG   [ZZ];                  // gathered bias
__device__ __align__(16) float g_zx   [(size_t)BB * TT * ZZ];// x@Wx + b, [t][b][gathered 2048] (512 MB)
__device__ __align__(16) bf16  g_hbuf [2 * BB * UU];         // double-buffered hidden state (bf16)
__device__ unsigned g_count;                                 // barrier arrival counter
__device__ unsigned g_release;                               // barrier release epoch

// gather map: gc -> original column
__device__ __forceinline__ int orig_col(int gc) {
    int cu   = gc >> 5;
    int gate = (gc >> 3) & 3;
    int j    = gc & 7;
    return gate * UU + cu * UT + j;
}

__device__ __forceinline__ float tanh_apx(float x) {
    float y;
    asm("tanh.approx.f32 %0, %1;" : "=f"(y) : "f"(x));
    return y;
}
__device__ __forceinline__ float sigm_apx(float x) {
    return fmaf(tanh_apx(0.5f * x), 0.5f, 0.5f);
}

__device__ __forceinline__ void mma_bf16(float& d0, float& d1, float& d2, float& d3,
                                         uint32_t a0, uint32_t a1, uint32_t a2, uint32_t a3,
                                         uint32_t b0, uint32_t b1) {
    asm volatile(
        "mma.sync.aligned.m16n8k16.row.col.f32.bf16.bf16.f32 "
        "{%0,%1,%2,%3}, {%4,%5,%6,%7}, {%8,%9}, {%0,%1,%2,%3};"
        : "+f"(d0), "+f"(d1), "+f"(d2), "+f"(d3)
        : "r"(a0), "r"(a1), "r"(a2), "r"(a3), "r"(b0), "r"(b1));
}

__device__ __forceinline__ void ldsm_x4(uint32_t& r0, uint32_t& r1, uint32_t& r2, uint32_t& r3,
                                        uint32_t addr) {
    asm volatile("ldmatrix.sync.aligned.m8n8.x4.shared.b16 {%0,%1,%2,%3}, [%4];"
                 : "=r"(r0), "=r"(r1), "=r"(r2), "=r"(r3) : "r"(addr));
}
__device__ __forceinline__ void ldsm_x2(uint32_t& r0, uint32_t& r1, uint32_t addr) {
    asm volatile("ldmatrix.sync.aligned.m8n8.x2.shared.b16 {%0,%1}, [%2];"
                 : "=r"(r0), "=r"(r1) : "r"(addr));
}

__device__ __forceinline__ uint32_t ldpair(const bf16* p) {
    return *(const uint32_t*)p;
}

__device__ __forceinline__ void cp_async16(uint32_t dst_smem, const void* src) {
    asm volatile("cp.async.cg.shared.global [%0], [%1], 16;" :: "r"(dst_smem), "l"(src));
}

// ---------------- init kernels ----------------
__global__ void k_cvt_emb(const float* __restrict__ src) {
    int n4 = 32000 * EE / 4;
    for (int i = blockIdx.x * blockDim.x + threadIdx.x; i < n4; i += gridDim.x * blockDim.x) {
        float4 v = *(const float4*)(src + (size_t)i * 4);
        bf16* d = g_emb16 + (size_t)i * 4;
        d[0] = __float2bfloat16(v.x);
        d[1] = __float2bfloat16(v.y);
        d[2] = __float2bfloat16(v.z);
        d[3] = __float2bfloat16(v.w);
    }
}

__global__ void k_gather_wx(const float* __restrict__ Wx, const float* __restrict__ bvec) {
    int n = ZZ * EE;
    for (int i = blockIdx.x * blockDim.x + threadIdx.x; i < n; i += gridDim.x * blockDim.x) {
        int gc = i >> 8;          // / 256
        int k  = i & 255;
        g_WxGt[i] = __float2bfloat16(Wx[(size_t)k * ZZ + orig_col(gc)]);
    }
    int t = blockIdx.x * blockDim.x + threadIdx.x;
    if (t < ZZ) g_bG[t] = bvec[orig_col(t)];
}

__global__ void k_gather_wh(const float* __restrict__ Wh) {
    int n = NCU * CPC * UU;
    for (int i = blockIdx.x * blockDim.x + threadIdx.x; i < n; i += gridDim.x * blockDim.x) {
        int cu = i >> 14;             // / (32*512)
        int jp = (i >> 9) & 31;
        int k  = i & 511;
        int gate = jp >> 3;
        int j    = jp & 7;
        g_WhGt[i] = __float2bfloat16(Wh[(size_t)k * ZZ + gate * UU + cu * UT + j]);
    }
}

__global__ void k_zero_state() {
    int tid = blockIdx.x * blockDim.x + threadIdx.x;
    int n = BB * UU;
    for (int i = tid; i < n; i += gridDim.x * blockDim.x)
        g_hbuf[i] = __float2bfloat16(0.0f);
    if (tid == 0) { g_count = 0; g_release = 0; }
}

// ---------------- phase 1: z_x = emb[sentence] @ Wx + b (gathered cols) ----------------
// grid 1024: n0 = (bx&31)*64, tbase = (bx>>5)*16. B tile resident; loop 16 timesteps.
// dyn smem: Bs 64x264 bf16 (33792 B) | As 128x72 bf16 (18432 B) | toks 128 int (512 B)
__global__ __launch_bounds__(256) void k_phase1(const int* __restrict__ sentence) {
    extern __shared__ __align__(16) char dsm[];
    bf16* Bs   = (bf16*)dsm;                       // stride 264
    bf16* As   = (bf16*)(dsm + 33792);             // stride 72
    int*  toks = (int*) (dsm + 33792 + 18432);

    int tid  = threadIdx.x;
    int warp = tid >> 5;
    int lane = tid & 31;
    int tg   = lane & 3;
    int gid  = lane >> 2;

    int n0    = (blockIdx.x & 31) * 64;
    int tbase = (blockIdx.x >> 5) * 16;

    int wm = (warp >> 1) * 32;
    int wn = (warp & 1) * 32;

    // stage B tile once: 64 gathered cols x 256 k
#pragma unroll
    for (int r = 0; r < 8; r++) {
        int i   = tid + 256 * r;
        int row = i >> 5;          // 32 uint4 per row
        int seg = i & 31;
        *(uint4*)(Bs + row * 264 + seg * 8) =
            *(const uint4*)(g_WxGt + (size_t)(n0 + row) * EE + seg * 8);
    }

    // hoist bias (per-thread constant across t)
    float bi[4][2];
#pragma unroll
    for (int nt = 0; nt < 4; nt++) {
        int col = n0 + wn + nt * 8 + tg * 2;
        bi[nt][0] = g_bG[col];
        bi[nt][1] = g_bG[col + 1];
    }
    __syncthreads();

    for (int tt = 0; tt < 16; tt++) {
        int t = tbase + tt;
        if (tid < 128) toks[tid] = sentence[tid * TT + t];
        __syncthreads();

        float acc[2][4][4];
#pragma unroll
        for (int mt = 0; mt < 2; mt++)
#pragma unroll
            for (int nt = 0; nt < 4; nt++)
#pragma unroll
                for (int q = 0; q < 4; q++) acc[mt][nt][q] = 0.0f;

        for (int kc = 0; kc < EE; kc += 64) {
            // stage A: 128 rows x 64 k
#pragma unroll
            for (int r = 0; r < 4; r++) {
                int i   = tid + 256 * r;
                int row = i >> 3;
                int seg = i & 7;
                *(uint4*)(As + row * 72 + seg * 8) =
                    *(const uint4*)(g_emb16 + (size_t)toks[row] * EE + kc + seg * 8);
            }
            __syncthreads();

#pragma unroll
            for (int k16 = 0; k16 < 4; k16++) {
                int kbA = k16 * 16;
                int kbB = kc + k16 * 16;
                uint32_t a[2][4];
#pragma unroll
                for (int mt = 0; mt < 2; mt++) {
                    const bf16* p = As + (wm + mt * 16 + gid) * 72 + kbA + tg * 2;
                    a[mt][0] = ldpair(p);
                    a[mt][1] = ldpair(p + 8 * 72);
                    a[mt][2] = ldpair(p + 8);
                    a[mt][3] = ldpair(p + 8 * 72 + 8);
                }
                uint32_t bfr[4][2];
#pragma unroll
                for (int nt = 0; nt < 4; nt++) {
                    const bf16* p = Bs + (wn + nt * 8 + gid) * 264 + kbB + tg * 2;
                    bfr[nt][0] = ldpair(p);
                    bfr[nt][1] = ldpair(p + 8);
                }
#pragma unroll
                for (int mt = 0; mt < 2; mt++)
#pragma unroll
                    for (int nt = 0; nt < 4; nt++)
                        mma_bf16(acc[mt][nt][0], acc[mt][nt][1], acc[mt][nt][2], acc[mt][nt][3],
                                 a[mt][0], a[mt][1], a[mt][2], a[mt][3],
                                 bfr[nt][0], bfr[nt][1]);
            }
            __syncthreads();
        }

        // epilogue
#pragma unroll
        for (int mt = 0; mt < 2; mt++) {
#pragma unroll
            for (int nt = 0; nt < 4; nt++) {
                int b   = wm + mt * 16 + gid;
                int col = n0 + wn + nt * 8 + tg * 2;
                size_t r0 = ((size_t)t * BB + b) * ZZ + col;
                size_t r2 = ((size_t)t * BB + b + 8) * ZZ + col;
                float2 v0 = { acc[mt][nt][0] + bi[nt][0], acc[mt][nt][1] + bi[nt][1] };
                float2 v2 = { acc[mt][nt][2] + bi[nt][0], acc[mt][nt][3] + bi[nt][1] };
                *(float2*)(g_zx + r0) = v0;
                *(float2*)(g_zx + r2) = v2;
            }
        }
    }
}

// ---------------- phase 2: persistent recurrence over all 512 steps ----------------
// dyn smem: Bs (Wh) 32x520 bf16 (33280 B) | hs 64x520 bf16 (66560 B) | zs 64x33 f32 (8448 B)
__global__ __launch_bounds__(256) void k_recur() {
    extern __shared__ __align__(16) char dsm[];
    bf16*  Bs = (bf16*)dsm;                        // Wh slice, stride 520
    bf16*  hs = (bf16*)(dsm + 33280);              // h tile, stride 520
    float* zs = (float*)(dsm + 33280 + 66560);     // z staging, stride 33

    uint32_t Bs_u32 = (uint32_t)__cvta_generic_to_shared(Bs);
    uint32_t hs_u32 = (uint32_t)__cvta_generic_to_shared(hs);

    int tid  = threadIdx.x;
    int warp = tid >> 5;
    int lane = tid & 31;
    int tg   = lane & 3;
    int gid  = lane >> 2;

    int cu = blockIdx.x & 63;
    int mg = blockIdx.x >> 6;
    int m0 = mg * 64;

    int wm = (warp >> 1) * 16;
    int wn = (warp & 1) * 16;

    // preload Wh slice (32 x 512 bf16)
    {
        const bf16* Wp = g_WhGt + (size_t)cu * CPC * UU;
        for (int i = tid; i < 2048; i += 256) {
            int n   = i >> 6;
            int seg = i & 63;
            *(uint4*)(Bs + n * 520 + seg * 8) = *(const uint4*)(Wp + n * UU + seg * 8);
        }
    }

    // ldmatrix lane addresses (byte offsets), invariant across steps
    uint32_t aAddrBase = hs_u32 + (uint32_t)(((wm + (lane & 15)) * 520 + ((lane & 16) ? 8 : 0)) * 2);
    uint32_t bAddr0    = Bs_u32 + (uint32_t)(((wn + 0 + (lane & 7)) * 520 + ((lane & 8) ? 8 : 0)) * 2);
    uint32_t bAddr1    = Bs_u32 + (uint32_t)(((wn + 8 + (lane & 7)) * 520 + ((lane & 8) ? 8 : 0)) * 2);

    // gate-update ownership
    int bl = tid >> 2;
    int jh = tid & 3;
    float c0 = 0.0f, c1 = 0.0f;

    for (int t = 0; t < TT; t++) {
        int p = t & 1;
        const bf16* hsrc = g_hbuf + p * (BB * UU);
        bf16*       hdst = g_hbuf + (p ^ 1) * (BB * UU);

        // prefetch z_x segment into registers (long slack before use)
        const float* zxp = g_zx + ((size_t)t * BB + m0 + bl) * ZZ + cu * CPC;
        float2 zx0 = *(const float2*)(zxp + 0  + jh * 2);
        float2 zx1 = *(const float2*)(zxp + 8  + jh * 2);
        float2 zx2 = *(const float2*)(zxp + 16 + jh * 2);
        float2 zx3 = *(const float2*)(zxp + 24 + jh * 2);

        // stage full h tile 64x512 via cp.async (L2-direct; also avoids stale L1)
#pragma unroll
        for (int r = 0; r < 16; r++) {
            int i   = r * 256 + tid;
            int row = i >> 6;
            int seg = i & 63;
            cp_async16(hs_u32 + (uint32_t)((row * 520 + seg * 8) * 2),
                       hsrc + (size_t)(m0 + row) * UU + seg * 8);
        }
        asm volatile("cp.async.commit_group;\ncp.async.wait_group 0;" ::: "memory");
        __syncthreads();

        float acc[2][4];
#pragma unroll
        for (int nt = 0; nt < 2; nt++)
#pragma unroll
            for (int q = 0; q < 4; q++) acc[nt][q] = 0.0f;

#pragma unroll 8
        for (int ks = 0; ks < 32; ks++) {
            uint32_t kboff = (uint32_t)(ks * 32);   // 16 bf16 = 32 bytes
            uint32_t a0, a1, a2, a3;
            ldsm_x4(a0, a1, a2, a3, aAddrBase + kboff);
            uint32_t b0, b1;
            ldsm_x2(b0, b1, bAddr0 + kboff);
            mma_bf16(acc[0][0], acc[0][1], acc[0][2], acc[0][3], a0, a1, a2, a3, b0, b1);
            uint32_t b2, b3;
            ldsm_x2(b2, b3, bAddr1 + kboff);
            mma_bf16(acc[1][0], acc[1][1], acc[1][2], acc[1][3], a0, a1, a2, a3, b2, b3);
        }

        // stage z (fp32) into zs
#pragma unroll
        for (int nt = 0; nt < 2; nt++) {
            int row = wm + gid;
            int col = wn + nt * 8 + tg * 2;
            zs[row * 33 + col]           = acc[nt][0];
            zs[row * 33 + col + 1]       = acc[nt][1];
            zs[(row + 8) * 33 + col]     = acc[nt][2];
            zs[(row + 8) * 33 + col + 1] = acc[nt][3];
        }
        __syncthreads();

        // gate update (c in registers)
        {
            const float* zr = zs + bl * 33;
            float hv0, hv1;
            {
                int jc = jh * 2;
                float zi = zx0.x + zr[jc];
                float zf = zx1.x + zr[8 + jc];
                float zg = zx2.x + zr[16 + jc];
                float zo = zx3.x + zr[24 + jc];
                float ig = sigm_apx(zi), fg = sigm_apx(zf);
                float gg = tanh_apx(zg), og = sigm_apx(zo);
                c0 = fg * c0 + ig * gg;
                hv0 = og * tanh_apx(c0);
            }
            {
                int jc = jh * 2 + 1;
                float zi = zx0.y + zr[jc];
                float zf = zx1.y + zr[8 + jc];
                float zg = zx2.y + zr[16 + jc];
                float zo = zx3.y + zr[24 + jc];
                float ig = sigm_apx(zi), fg = sigm_apx(zf);
                float gg = tanh_apx(zg), og = sigm_apx(zo);
                c1 = fg * c1 + ig * gg;
                hv1 = og * tanh_apx(c1);
            }
            __nv_bfloat162 h2;
            h2.x = __float2bfloat16(hv0);
            h2.y = __float2bfloat16(hv1);
            *(__nv_bfloat162*)(hdst + (size_t)(m0 + bl) * UU + cu * UT + jh * 2) = h2;
        }
        __syncthreads();   // all h stores issued

        // grid-wide barrier
        if (tid == 0) {
            __threadfence();
            unsigned arr = atomicAdd(&g_count, 1u);
            if (arr == NCTA - 1) {
                g_count = 0;
                __threadfence();
                *(volatile unsigned*)&g_release = (unsigned)(t + 1);
            } else {
                while (*(volatile unsigned*)&g_release < (unsigned)(t + 1)) { }
                __threadfence();
            }
        }
        __syncthreads();
    }
}

// ---------------- head: per-batch MLP ----------------
__global__ __launch_bounds__(128) void k_head(const float* __restrict__ W1, const float* __restrict__ b1,
                                              const float* __restrict__ W2, const float* __restrict__ b2,
                                              const float* __restrict__ W3, const float* __restrict__ b3,
                                              float* __restrict__ out) {
    __shared__ float hs[UU];
    __shared__ float h1[128];
    __shared__ float red[64];
    int b   = blockIdx.x;
    int tid = threadIdx.x;

    for (int i = tid; i < UU; i += 128) hs[i] = __bfloat162float(g_hbuf[b * UU + i]);
    __syncthreads();

    float a1 = b1[tid];
#pragma unroll 8
    for (int k = 0; k < UU; k++) a1 += hs[k] * W1[k * 128 + tid];
    h1[tid] = fmaxf(a1, 0.0f);
    __syncthreads();

    if (tid < 64) {
        float a2 = b2[tid];
#pragma unroll 8
        for (int k = 0; k < 128; k++) a2 += h1[k] * W2[k * 64 + tid];
        a2 = fmaxf(a2, 0.0f);
        red[tid] = a2 * W3[tid];
    }
    __syncthreads();

    if (tid == 0) {
        float s = b3[0];
#pragma unroll 8
        for (int k = 0; k < 64; k++) s += red[k];
        out[b] = 1.0f / (1.0f + expf(-s));
    }
}

// ---------------- launch ----------------
extern "C" void kernel_launch(void* const* d_in, const int* in_sizes, int n_in,
                              void* d_out, int out_size) {
    const int*   sentence = (const int*)  d_in[0];
    const float* emb      = (const float*)d_in[1];
    const float* Wx       = (const float*)d_in[2];
    const float* Wh       = (const float*)d_in[3];
    const float* bvec     = (const float*)d_in[4];
    const float* W1       = (const float*)d_in[5];
    const float* b1       = (const float*)d_in[6];
    const float* W2       = (const float*)d_in[7];
    const float* b2       = (const float*)d_in[8];
    const float* W3       = (const float*)d_in[9];
    const float* b3       = (const float*)d_in[10];
    float* out = (float*)d_out;

    static bool attr_done = false;
    if (!attr_done) {
        cudaFuncSetAttribute(k_phase1, cudaFuncAttributeMaxDynamicSharedMemorySize, 52736);
        cudaFuncSetAttribute(k_recur,  cudaFuncAttributeMaxDynamicSharedMemorySize, 108288);
        attr_done = true;
    }

    k_cvt_emb<<<4096, 256>>>(emb);
    k_gather_wx<<<2048, 256>>>(Wx, bvec);
    k_gather_wh<<<4096, 256>>>(Wh);
    k_zero_state<<<256, 256>>>();

    k_phase1<<<1024, 256, 52736>>>(sentence);

    k_recur<<<NCTA, 256, 108288>>>();

    k_head<<<128, 128>>>(W1, b1, W2, b2, W3, b3, out);
}

// round 5
// speedup vs baseline: 5.1915x; 1.2759x over previous
#include <cuda_runtime.h>
#include <cuda_bf16.h>
#include <cstdint>
#include <cstddef>

// Problem dims
#define BB   128
#define TT   512
#define EE   256
#define UU   512
#define ZZ   2048          // 4*U
#define NCU  64            // u-groups (8 units each)
#define UT   8             // units per CTA group
#define CPC  32            // z-cols per CTA (4 gates * 8 units)
#define NCTA 128           // persistent grid

typedef __nv_bfloat16 bf16;

// ---------------- scratch (device globals; no allocations) ----------------
__device__ __align__(16) bf16  g_emb16[32000 * EE];          // bf16 embedding (16.4 MB)
__device__ __align__(16) bf16  g_WxGt [ZZ * EE];             // gathered Wx, [gc][k] (1 MB)
__device__ __align__(16) bf16  g_WhGt [NCU * CPC * UU];      // gathered Wh, [cu][jp][k] (2 MB)
__device__ __align__(16) float g_bG   [ZZ];                  // gathered bias
__device__ __align__(16) float g_zx   [(size_t)BB * TT * ZZ];// x@Wx + b, [t][b][gathered 2048] (512 MB)
__device__ __align__(16) bf16  g_hbuf [2 * BB * UU];         // double-buffered hidden state (bf16)
__device__ __align__(16) unsigned g_flags[NCTA * 32];        // per-CTA epoch flags, 128B padded

// gather map: gc -> original column
__device__ __forceinline__ int orig_col(int gc) {
    int cu   = gc >> 5;
    int gate = (gc >> 3) & 3;
    int j    = gc & 7;
    return gate * UU + cu * UT + j;
}

__device__ __forceinline__ float tanh_apx(float x) {
    float y;
    asm("tanh.approx.f32 %0, %1;" : "=f"(y) : "f"(x));
    return y;
}
__device__ __forceinline__ float sigm_apx(float x) {
    return fmaf(tanh_apx(0.5f * x), 0.5f, 0.5f);
}

__device__ __forceinline__ void mma_bf16(float& d0, float& d1, float& d2, float& d3,
                                         uint32_t a0, uint32_t a1, uint32_t a2, uint32_t a3,
                                         uint32_t b0, uint32_t b1) {
    asm volatile(
        "mma.sync.aligned.m16n8k16.row.col.f32.bf16.bf16.f32 "
        "{%0,%1,%2,%3}, {%4,%5,%6,%7}, {%8,%9}, {%0,%1,%2,%3};"
        : "+f"(d0), "+f"(d1), "+f"(d2), "+f"(d3)
        : "r"(a0), "r"(a1), "r"(a2), "r"(a3), "r"(b0), "r"(b1));
}

__device__ __forceinline__ void ldsm_x4(uint32_t& r0, uint32_t& r1, uint32_t& r2, uint32_t& r3,
                                        uint32_t addr) {
    asm volatile("ldmatrix.sync.aligned.m8n8.x4.shared.b16 {%0,%1,%2,%3}, [%4];"
                 : "=r"(r0), "=r"(r1), "=r"(r2), "=r"(r3) : "r"(addr));
}

__device__ __forceinline__ uint32_t ldpair(const bf16* p) {
    return *(const uint32_t*)p;
}

__device__ __forceinline__ void cp_async16(uint32_t dst_smem, const void* src) {
    asm volatile("cp.async.cg.shared.global [%0], [%1], 16;" :: "r"(dst_smem), "l"(src));
}

// ---------------- init kernels ----------------
__global__ void k_cvt_emb(const float* __restrict__ src) {
    int n4 = 32000 * EE / 4;
    for (int i = blockIdx.x * blockDim.x + threadIdx.x; i < n4; i += gridDim.x * blockDim.x) {
        float4 v = *(const float4*)(src + (size_t)i * 4);
        bf16* d = g_emb16 + (size_t)i * 4;
        d[0] = __float2bfloat16(v.x);
        d[1] = __float2bfloat16(v.y);
        d[2] = __float2bfloat16(v.z);
        d[3] = __float2bfloat16(v.w);
    }
}

__global__ void k_gather_wx(const float* __restrict__ Wx, const float* __restrict__ bvec) {
    int n = ZZ * EE;
    for (int i = blockIdx.x * blockDim.x + threadIdx.x; i < n; i += gridDim.x * blockDim.x) {
        int gc = i >> 8;          // / 256
        int k  = i & 255;
        g_WxGt[i] = __float2bfloat16(Wx[(size_t)k * ZZ + orig_col(gc)]);
    }
    int t = blockIdx.x * blockDim.x + threadIdx.x;
    if (t < ZZ) g_bG[t] = bvec[orig_col(t)];
}

__global__ void k_gather_wh(const float* __restrict__ Wh) {
    int n = NCU * CPC * UU;
    for (int i = blockIdx.x * blockDim.x + threadIdx.x; i < n; i += gridDim.x * blockDim.x) {
        int cu = i >> 14;             // / (32*512)
        int jp = (i >> 9) & 31;
        int k  = i & 511;
        int gate = jp >> 3;
        int j    = jp & 7;
        g_WhGt[i] = __float2bfloat16(Wh[(size_t)k * ZZ + gate * UU + cu * UT + j]);
    }
}

__global__ void k_zero_state() {
    int tid = blockIdx.x * blockDim.x + threadIdx.x;
    int n = BB * UU;
    for (int i = tid; i < n; i += gridDim.x * blockDim.x)
        g_hbuf[i] = __float2bfloat16(0.0f);
    for (int i = tid; i < NCTA * 32; i += gridDim.x * blockDim.x)
        g_flags[i] = 0u;
}

// ---------------- phase 1: z_x = emb[sentence] @ Wx + b (gathered cols) ----------------
// grid 1024: n0 = (bx&31)*64, tbase = (bx>>5)*16. B tile resident; loop 16 timesteps.
__global__ __launch_bounds__(256) void k_phase1(const int* __restrict__ sentence) {
    extern __shared__ __align__(16) char dsm[];
    bf16* Bs   = (bf16*)dsm;                       // stride 264
    bf16* As   = (bf16*)(dsm + 33792);             // stride 72
    int*  toks = (int*) (dsm + 33792 + 18432);

    int tid  = threadIdx.x;
    int warp = tid >> 5;
    int lane = tid & 31;
    int tg   = lane & 3;
    int gid  = lane >> 2;

    int n0    = (blockIdx.x & 31) * 64;
    int tbase = (blockIdx.x >> 5) * 16;

    int wm = (warp >> 1) * 32;
    int wn = (warp & 1) * 32;

#pragma unroll
    for (int r = 0; r < 8; r++) {
        int i   = tid + 256 * r;
        int row = i >> 5;
        int seg = i & 31;
        *(uint4*)(Bs + row * 264 + seg * 8) =
            *(const uint4*)(g_WxGt + (size_t)(n0 + row) * EE + seg * 8);
    }

    float bi[4][2];
#pragma unroll
    for (int nt = 0; nt < 4; nt++) {
        int col = n0 + wn + nt * 8 + tg * 2;
        bi[nt][0] = g_bG[col];
        bi[nt][1] = g_bG[col + 1];
    }
    __syncthreads();

    for (int tt = 0; tt < 16; tt++) {
        int t = tbase + tt;
        if (tid < 128) toks[tid] = sentence[tid * TT + t];
        __syncthreads();

        float acc[2][4][4];
#pragma unroll
        for (int mt = 0; mt < 2; mt++)
#pragma unroll
            for (int nt = 0; nt < 4; nt++)
#pragma unroll
                for (int q = 0; q < 4; q++) acc[mt][nt][q] = 0.0f;

        for (int kc = 0; kc < EE; kc += 64) {
#pragma unroll
            for (int r = 0; r < 4; r++) {
                int i   = tid + 256 * r;
                int row = i >> 3;
                int seg = i & 7;
                *(uint4*)(As + row * 72 + seg * 8) =
                    *(const uint4*)(g_emb16 + (size_t)toks[row] * EE + kc + seg * 8);
            }
            __syncthreads();

#pragma unroll
            for (int k16 = 0; k16 < 4; k16++) {
                int kbA = k16 * 16;
                int kbB = kc + k16 * 16;
                uint32_t a[2][4];
#pragma unroll
                for (int mt = 0; mt < 2; mt++) {
                    const bf16* p = As + (wm + mt * 16 + gid) * 72 + kbA + tg * 2;
                    a[mt][0] = ldpair(p);
                    a[mt][1] = ldpair(p + 8 * 72);
                    a[mt][2] = ldpair(p + 8);
                    a[mt][3] = ldpair(p + 8 * 72 + 8);
                }
                uint32_t bfr[4][2];
#pragma unroll
                for (int nt = 0; nt < 4; nt++) {
                    const bf16* p = Bs + (wn + nt * 8 + gid) * 264 + kbB + tg * 2;
                    bfr[nt][0] = ldpair(p);
                    bfr[nt][1] = ldpair(p + 8);
                }
#pragma unroll
                for (int mt = 0; mt < 2; mt++)
#pragma unroll
                    for (int nt = 0; nt < 4; nt++)
                        mma_bf16(acc[mt][nt][0], acc[mt][nt][1], acc[mt][nt][2], acc[mt][nt][3],
                                 a[mt][0], a[mt][1], a[mt][2], a[mt][3],
                                 bfr[nt][0], bfr[nt][1]);
            }
            __syncthreads();
        }

#pragma unroll
        for (int mt = 0; mt < 2; mt++) {
#pragma unroll
            for (int nt = 0; nt < 4; nt++) {
                int b   = wm + mt * 16 + gid;
                int col = n0 + wn + nt * 8 + tg * 2;
                size_t r0 = ((size_t)t * BB + b) * ZZ + col;
                size_t r2 = ((size_t)t * BB + b + 8) * ZZ + col;
                float2 v0 = { acc[mt][nt][0] + bi[nt][0], acc[mt][nt][1] + bi[nt][1] };
                float2 v2 = { acc[mt][nt][2] + bi[nt][0], acc[mt][nt][3] + bi[nt][1] };
                *(float2*)(g_zx + r0) = v0;
                *(float2*)(g_zx + r2) = v2;
            }
        }
    }
}

// ---------------- phase 2: persistent recurrence ----------------
// 128 CTAs x 128 threads. cu = bx&63, mg = bx>>6 (independent half-batch group).
// CTA tile 64x32; 4 warps, warp tile 16x32 where the 4 n8-tiles == the 4 gates.
// Gate math entirely in registers. Flag-array barrier per group.
// dyn smem: Bs (Wh) 32x520 bf16 (33280 B) | hs 64x520 bf16 (66560 B)
__global__ __launch_bounds__(128) void k_recur() {
    extern __shared__ __align__(16) char dsm[];
    bf16* Bs = (bf16*)dsm;                        // Wh slice, stride 520
    bf16* hs = (bf16*)(dsm + 33280);              // h tile, stride 520

    uint32_t Bs_u32 = (uint32_t)__cvta_generic_to_shared(Bs);
    uint32_t hs_u32 = (uint32_t)__cvta_generic_to_shared(hs);

    int tid  = threadIdx.x;
    int warp = tid >> 5;
    int lane = tid & 31;
    int tg   = lane & 3;
    int gid  = lane >> 2;

    int cu = blockIdx.x & 63;
    int mg = blockIdx.x >> 6;
    int m0 = mg * 64;
    int wm = warp * 16;

    // preload Wh slice (32 x 512 bf16)
    {
        const bf16* Wp = g_WhGt + (size_t)cu * CPC * UU;
        for (int i = tid; i < 2048; i += 128) {
            int n   = i >> 6;
            int seg = i & 63;
            *(uint4*)(Bs + n * 520 + seg * 8) = *(const uint4*)(Wp + n * UU + seg * 8);
        }
    }

    // ldmatrix lane addresses (byte offsets), invariant across steps
    uint32_t aAddr = hs_u32 + (uint32_t)((wm + (lane & 15)) * 520 * 2 + ((lane & 16) ? 16 : 0));
    // B: two ldsm_x4 covering 4 gate tiles. g=0 -> rows 0..15 (gates i,f), g=1 -> rows 16..31 (g,o)
    uint32_t bAddr0 = Bs_u32 + (uint32_t)(((0  + (lane & 7) + ((lane & 16) ? 8 : 0)) * 520) * 2 + ((lane & 8) ? 16 : 0));
    uint32_t bAddr1 = Bs_u32 + (uint32_t)(((16 + (lane & 7) + ((lane & 16) ? 8 : 0)) * 520) * 2 + ((lane & 8) ? 16 : 0));

    // this lane owns rows (m0+wm+gid, +8) and units (cu*8 + tg*2, +1)
    int rowA = m0 + wm + gid;
    float c00 = 0.0f, c01 = 0.0f, c10 = 0.0f, c11 = 0.0f;

    unsigned* myflag   = g_flags + (size_t)(mg * 64 + cu) * 32;
    unsigned* pollflag = g_flags + (size_t)(mg * 64 + (tid & 63)) * 32;

    for (int t = 0; t < TT; t++) {
        int p = t & 1;
        const bf16* hsrc = g_hbuf + p * (BB * UU);
        bf16*       hdst = g_hbuf + (p ^ 1) * (BB * UU);

        // prefetch z_x for this lane's rows/units (long slack before use)
        const float* zxr0 = g_zx + ((size_t)t * BB + rowA) * ZZ + cu * CPC + tg * 2;
        const float* zxr1 = zxr0 + 8 * ZZ;
        float2 zi0 = *(const float2*)(zxr0);
        float2 zf0 = *(const float2*)(zxr0 + 8);
        float2 zg0 = *(const float2*)(zxr0 + 16);
        float2 zo0 = *(const float2*)(zxr0 + 24);
        float2 zi1 = *(const float2*)(zxr1);
        float2 zf1 = *(const float2*)(zxr1 + 8);
        float2 zg1 = *(const float2*)(zxr1 + 16);
        float2 zo1 = *(const float2*)(zxr1 + 24);

        // stage h tile 64x512 via cp.async in 4 chunks of 128 cols
#pragma unroll
        for (int c = 0; c < 4; c++) {
#pragma unroll
            for (int r = 0; r < 8; r++) {
                int i   = r * 128 + tid;     // 0..1023
                int row = i >> 4;
                int seg = i & 15;
                cp_async16(hs_u32 + (uint32_t)((row * 520 + c * 128 + seg * 8) * 2),
                           hsrc + (size_t)(m0 + row) * UU + c * 128 + seg * 8);
            }
            asm volatile("cp.async.commit_group;" ::: "memory");
        }

        float ai0 = 0, ai1 = 0, ai2 = 0, ai3 = 0;   // gate i acc
        float af0 = 0, af1 = 0, af2 = 0, af3 = 0;   // gate f
        float ag0 = 0, ag1 = 0, ag2 = 0, ag3 = 0;   // gate g
        float ao0 = 0, ao1 = 0, ao2 = 0, ao3 = 0;   // gate o

#define COMPUTE_CHUNK(CC, WG)                                                       \
        asm volatile("cp.async.wait_group " #WG ";" ::: "memory");                  \
        __syncthreads();                                                            \
        _Pragma("unroll")                                                           \
        for (int ks = CC * 8; ks < CC * 8 + 8; ks++) {                              \
            uint32_t kb = (uint32_t)(ks * 32);                                      \
            uint32_t a0, a1, a2, a3, b0, b1, b2, b3, b4, b5, b6, b7;                \
            ldsm_x4(a0, a1, a2, a3, aAddr + kb);                                    \
            ldsm_x4(b0, b1, b2, b3, bAddr0 + kb);                                   \
            ldsm_x4(b4, b5, b6, b7, bAddr1 + kb);                                   \
            mma_bf16(ai0, ai1, ai2, ai3, a0, a1, a2, a3, b0, b1);                   \
            mma_bf16(af0, af1, af2, af3, a0, a1, a2, a3, b2, b3);                   \
            mma_bf16(ag0, ag1, ag2, ag3, a0, a1, a2, a3, b4, b5);                   \
            mma_bf16(ao0, ao1, ao2, ao3, a0, a1, a2, a3, b6, b7);                   \
        }

        COMPUTE_CHUNK(0, 3)
        COMPUTE_CHUNK(1, 2)
        COMPUTE_CHUNK(2, 1)
        COMPUTE_CHUNK(3, 0)
#undef COMPUTE_CHUNK

        // gate update fully in registers
        {
            // row gid, unit tg*2 / tg*2+1
            float i0 = sigm_apx(zi0.x + ai0), f0 = sigm_apx(zf0.x + af0);
            float gg0 = tanh_apx(zg0.x + ag0), o0 = sigm_apx(zo0.x + ao0);
            c00 = f0 * c00 + i0 * gg0;
            float h00 = o0 * tanh_apx(c00);

            float i1 = sigm_apx(zi0.y + ai1), f1 = sigm_apx(zf0.y + af1);
            float gg1 = tanh_apx(zg0.y + ag1), o1 = sigm_apx(zo0.y + ao1);
            c01 = f1 * c01 + i1 * gg1;
            float h01 = o1 * tanh_apx(c01);

            // row gid+8
            float i2 = sigm_apx(zi1.x + ai2), f2 = sigm_apx(zf1.x + af2);
            float gg2 = tanh_apx(zg1.x + ag2), o2 = sigm_apx(zo1.x + ao2);
            c10 = f2 * c10 + i2 * gg2;
            float h10 = o2 * tanh_apx(c10);

            float i3 = sigm_apx(zi1.y + ai3), f3 = sigm_apx(zf1.y + af3);
            float gg3 = tanh_apx(zg1.y + ag3), o3 = sigm_apx(zo1.y + ao3);
            c11 = f3 * c11 + i3 * gg3;
            float h11 = o3 * tanh_apx(c11);

            __nv_bfloat162 hA, hB;
            hA.x = __float2bfloat16(h00); hA.y = __float2bfloat16(h01);
            hB.x = __float2bfloat16(h10); hB.y = __float2bfloat16(h11);
            size_t base = (size_t)rowA * UU + cu * UT + tg * 2;
            *(__nv_bfloat162*)(hdst + base)          = hA;
            *(__nv_bfloat162*)(hdst + base + 8 * UU) = hB;
        }

        // group barrier: flag-array, contention-free
        __syncthreads();
        if (tid == 0) {
            asm volatile("st.release.gpu.u32 [%0], %1;" :: "l"(myflag), "r"(t + 1) : "memory");
        }
        if (tid < 64) {
            unsigned v;
            do {
                asm volatile("ld.acquire.gpu.u32 %0, [%1];" : "=r"(v) : "l"(pollflag));
            } while (v < (unsigned)(t + 1));
        }
        __syncthreads();
    }
}

// ---------------- head: per-batch MLP ----------------
__global__ __launch_bounds__(128) void k_head(const float* __restrict__ W1, const float* __restrict__ b1,
                                              const float* __restrict__ W2, const float* __restrict__ b2,
                                              const float* __restrict__ W3, const float* __restrict__ b3,
                                              float* __restrict__ out) {
    __shared__ float hs[UU];
    __shared__ float h1[128];
    __shared__ float red[64];
    int b   = blockIdx.x;
    int tid = threadIdx.x;

    for (int i = tid; i < UU; i += 128) hs[i] = __bfloat162float(g_hbuf[b * UU + i]);
    __syncthreads();

    float a1 = b1[tid];
#pragma unroll 8
    for (int k = 0; k < UU; k++) a1 += hs[k] * W1[k * 128 + tid];
    h1[tid] = fmaxf(a1, 0.0f);
    __syncthreads();

    if (tid < 64) {
        float a2 = b2[tid];
#pragma unroll 8
        for (int k = 0; k < 128; k++) a2 += h1[k] * W2[k * 64 + tid];
        a2 = fmaxf(a2, 0.0f);
        red[tid] = a2 * W3[tid];
    }
    __syncthreads();

    if (tid == 0) {
        float s = b3[0];
#pragma unroll 8
        for (int k = 0; k < 64; k++) s += red[k];
        out[b] = 1.0f / (1.0f + expf(-s));
    }
}

// ---------------- launch ----------------
extern "C" void kernel_launch(void* const* d_in, const int* in_sizes, int n_in,
                              void* d_out, int out_size) {
    const int*   sentence = (const int*)  d_in[0];
    const float* emb      = (const float*)d_in[1];
    const float* Wx       = (const float*)d_in[2];
    const float* Wh       = (const float*)d_in[3];
    const float* bvec     = (const float*)d_in[4];
    const float* W1       = (const float*)d_in[5];
    const float* b1       = (const float*)d_in[6];
    const float* W2       = (const float*)d_in[7];
    const float* b2       = (const float*)d_in[8];
    const float* W3       = (const float*)d_in[9];
    const float* b3       = (const float*)d_in[10];
    float* out = (float*)d_out;

    static bool attr_done = false;
    if (!attr_done) {
        cudaFuncSetAttribute(k_phase1, cudaFuncAttributeMaxDynamicSharedMemorySize, 52736);
        cudaFuncSetAttribute(k_recur,  cudaFuncAttributeMaxDynamicSharedMemorySize, 99840);
        attr_done = true;
    }

    k_cvt_emb<<<4096, 256>>>(emb);
    k_gather_wx<<<2048, 256>>>(Wx, bvec);
    k_gather_wh<<<4096, 256>>>(Wh);
    k_zero_state<<<256, 256>>>();

    k_phase1<<<1024, 256, 52736>>>(sentence);

    k_recur<<<NCTA, 128, 99840>>>();

    k_head<<<128, 128>>>(W1, b1, W2, b2, W3, b3, out);
}